// round 10
// baseline (speedup 1.0000x reference)
#include <cuda_runtime.h>
#include <math.h>

#define BB 64
#define NNODES 512
#define BN 32768
#define EE 524288
#define DA 70
#define DE 14
#define DH 200
#define DI 6
#define TSCALE 0.07071067811865475f

typedef unsigned long long ull;
typedef unsigned int uint;

__device__ __forceinline__ ull fma2(ull a, ull b, ull c) {
    ull d; asm("fma.rn.f32x2 %0, %1, %2, %3;" : "=l"(d) : "l"(a), "l"(b), "l"(c)); return d;
}
__device__ __forceinline__ ull pack2(float x, float y) {
    ull r; asm("mov.b64 %0, {%1, %2};" : "=l"(r) : "f"(x), "f"(y)); return r;
}
__device__ __forceinline__ float2 unp2(ull a) {
    float2 f; asm("mov.b64 {%0, %1}, %2;" : "=f"(f.x), "=f"(f.y) : "l"(a)); return f;
}
__device__ __forceinline__ ull ld2s(const float* p) { return *reinterpret_cast<const ull*>(p); }

__device__ __forceinline__ void mma_tf32(float* d, uint a0, uint a1, uint a2, uint a3,
                                         uint b0, uint b1) {
    asm volatile("mma.sync.aligned.m16n8k8.row.col.f32.tf32.tf32.f32 "
                 "{%0,%1,%2,%3}, {%4,%5,%6,%7}, {%8,%9}, {%0,%1,%2,%3};"
                 : "+f"(d[0]), "+f"(d[1]), "+f"(d[2]), "+f"(d[3])
                 : "r"(a0), "r"(a1), "r"(a2), "r"(a3), "r"(b0), "r"(b1));
}
__device__ __forceinline__ void bsplit(float b, uint& hi, uint& lo) {
    uint bb = __float_as_uint(b);
    hi = bb & 0xFFFFE000u;
    lo = __float_as_uint(b - __uint_as_float(hi));
}

__device__ float g_h[2][BN * DH];
__device__ int   g_deg[2][BN];
__device__ int   g_cnt[2][BN];
__device__ int   g_rowptr[2][BN + 1];
__device__ int   g_cursor[2][BN];
__device__ int   g_eidx[2][EE];
__device__ float g_part[2][BB][16][DH];
__device__ int   g_flag[2];

// ---------------- atom GEMM + LN + edge counting + flag reset ----------------
__global__ void __launch_bounds__(256) k_atom(const float* __restrict__ a1,
                                              const float* __restrict__ a2,
                                              const int* __restrict__ d1,
                                              const int* __restrict__ d2,
                                              const float* __restrict__ W,
                                              const float* __restrict__ lng,
                                              const float* __restrict__ lnb) {
    extern __shared__ float sm[];
    float* sW = sm;
    float* sA = sm + DA * DH;
    int side = blockIdx.y;
    const float* atom = side ? a2 : a1;
    const int* dst = side ? d2 : d1;
    float* out = g_h[side];
    int t = threadIdx.x;
    if (blockIdx.x == 0 && t == 0) g_flag[side] = 0;
    {
        int e0 = blockIdx.x * 256 + t;
#pragma unroll
        for (int r = 0; r < 2; r++) atomicAdd(&g_cnt[side][dst[e0 + r * 262144]], 1);
    }
    for (int i = t; i < DA * DH; i += 256) sW[i] = W[i];
    int w = t / 32, l = t % 32;
    float lg[7], lb[7];
#pragma unroll
    for (int i = 0; i < 7; i++) {
        int k = l + 32 * i;
        lg[i] = (k < DH) ? lng[k] : 0.f;
        lb[i] = (k < DH) ? lnb[k] : 0.f;
    }
    __syncthreads();
    float* myA = sA + w * 2 * DA;
    for (int pair = 0; pair < 2; pair++) {
        int n0 = (blockIdx.x * 8 + w) * 4 + pair * 2;
        for (int j = l; j < 2 * DA; j += 32) myA[j] = atom[n0 * DA + j];
        __syncwarp();
        float a0[7], a1v[7];
#pragma unroll
        for (int i = 0; i < 7; i++) { a0[i] = 0.f; a1v[i] = 0.f; }
        for (int j = 0; j < DA; j++) {
            float x0 = myA[j], x1 = myA[DA + j];
#pragma unroll
            for (int i = 0; i < 7; i++) {
                int k = l + 32 * i;
                if (k < DH) {
                    float wv = sW[j * DH + k];
                    a0[i] = fmaf(x0, wv, a0[i]);
                    a1v[i] = fmaf(x1, wv, a1v[i]);
                }
            }
        }
#pragma unroll
        for (int nn = 0; nn < 2; nn++) {
            float* acc = nn ? a1v : a0;
            float s = 0.f, s2v = 0.f;
#pragma unroll
            for (int i = 0; i < 7; i++) {
                int k = l + 32 * i;
                if (k < DH) { float v = fmaxf(acc[i], 0.f); acc[i] = v; s += v; s2v += v * v; }
            }
#pragma unroll
            for (int o = 16; o > 0; o >>= 1) {
                s += __shfl_xor_sync(0xffffffffu, s, o);
                s2v += __shfl_xor_sync(0xffffffffu, s2v, o);
            }
            float m = s * (1.0f / DH);
            float rs = rsqrtf(s2v * (1.0f / DH) - m * m + 1e-5f);
#pragma unroll
            for (int i = 0; i < 7; i++) {
                int k = l + 32 * i;
                if (k < DH) out[(n0 + nn) * DH + k] = lg[i] * (acc[i] - m) * rs + lb[i];
            }
        }
        __syncwarp();
    }
}

// ---------------- merged CSR scan + fill ----------------
__global__ void __launch_bounds__(1024) k_scanfill(const int* __restrict__ d1,
                                                   const int* __restrict__ d2) {
    int t = threadIdx.x;
    if (blockIdx.x < 2) {
        int side = blockIdx.x;
        __shared__ int ws[32];
        int base = t * 32;
        int loc[32];
        int sum = 0;
#pragma unroll
        for (int i = 0; i < 32; i++) { loc[i] = g_cnt[side][base + i]; sum += loc[i]; }
        int l = t & 31, w = t >> 5;
        int v = sum;
#pragma unroll
        for (int off = 1; off < 32; off <<= 1) {
            int n = __shfl_up_sync(0xffffffffu, v, off);
            if (l >= off) v += n;
        }
        if (l == 31) ws[w] = v;
        __syncthreads();
        if (w == 0) {
            int x = ws[l];
#pragma unroll
            for (int off = 1; off < 32; off <<= 1) {
                int n = __shfl_up_sync(0xffffffffu, x, off);
                if (l >= off) x += n;
            }
            ws[l] = x;
        }
        __syncthreads();
        int run = v - sum + (w > 0 ? ws[w - 1] : 0);
        for (int i = 0; i < 32; i++) {
            g_rowptr[side][base + i] = run;
            g_cursor[side][base + i] = run;
            run += loc[i];
        }
        if (t == 1023) g_rowptr[side][BN] = run;
        __threadfence();
        __syncthreads();
        if (t == 0) atomicExch(&g_flag[side], 1);
    } else {
        int fb = blockIdx.x - 2;
        int side = fb >> 9;
        int slice = fb & 511;
        const int* dst = side ? d2 : d1;
        if (t == 0) { while (atomicAdd(&g_flag[side], 0) == 0) __nanosleep(128); }
        __syncthreads();
        int e = slice * 1024 + t;
        int slot = atomicAdd(&g_cursor[side][dst[e]], 1);
        g_eidx[side][slot] = e;
        if (t < 64) g_cnt[side][slice * 64 + t] = 0;
    }
}

// ---------------- edge gather: f32x2 packed over edges ----------------
__global__ void __launch_bounds__(128, 6) k_gather(
        const float* __restrict__ ef1, const float* __restrict__ ef2,
        const float* __restrict__ co1, const float* __restrict__ co2,
        const int* __restrict__ s1, const int* __restrict__ s2,
        const float* __restrict__ W_edge, const float* __restrict__ W_rbf,
        const float* __restrict__ b_rbf,
        const float* __restrict__ lng, const float* __restrict__ lnb) {
    __shared__ float sWall[16][224];
    __shared__ __align__(16) ull sE[4][2][16];
    __shared__ __align__(16) ull sR[4][2][16];

    int side = blockIdx.y;
    const float* ef     = side ? ef2 : ef1;
    const float* coords = side ? co2 : co1;
    const int*   esrc   = side ? s2 : s1;
    const int*   eidx   = g_eidx[side];
    const int*   rowptr = g_rowptr[side];
    float* h = g_h[side];
    int t = threadIdx.x, w = t >> 5, l = t & 31;

    for (int idx = t; idx < 16 * 224; idx += 128) {
        int j = idx / 224, k = idx % 224;
        float v = 0.f;
        if (k < 100) { if (j < DE) v = W_edge[j * 100 + k]; }
        else if (k < 200) v = W_rbf[j * 100 + (k - 100)];
        sWall[j][k] = v;
    }
    float bias[7], lg[7], lb[7];
#pragma unroll
    for (int i = 0; i < 7; i++) {
        int k = l + 32 * i;
        bias[i] = (k >= 100 && k < 200) ? b_rbf[k - 100] : 0.f;
        lg[i] = (k < DH) ? lng[k] : 0.f;
        lb[i] = (k < DH) ? lnb[k] : 0.f;
    }
    bool e3 = (l < 4);
    __syncthreads();

    int wg = blockIdx.x * 4 + w;
    int nw = gridDim.x * 4;
    for (int node = wg; node < BN; node += nw) {
        int r0 = rowptr[node], r1 = rowptr[node + 1];
        int deg = r1 - r0;
        float TA[7];
#pragma unroll
        for (int i = 0; i < 7; i++) TA[i] = 0.f;
        float sumMRS = 0.f;

        if (deg > 0) {
            float cdx = coords[node * 3 + 0];
            float cdy = coords[node * 3 + 1];
            float cdz = coords[node * 3 + 2];
            int ng = (deg + 3) >> 2;
            int nei[4], nsi[4];
            float efd[4], csx[4], csy[4], csz[4];
            {
                int ei0[4];
#pragma unroll
                for (int jj = 0; jj < 4; jj++) {
                    int e = r0 + jj; if (e > r1 - 1) e = r1 - 1;
                    ei0[jj] = eidx[e];
                }
#pragma unroll
                for (int jj = 0; jj < 4; jj++) {
                    int srcn = esrc[ei0[jj]];
                    efd[jj] = (l < DE) ? ef[ei0[jj] * DE + l] : 0.f;
                    csx[jj] = coords[srcn * 3 + 0];
                    csy[jj] = coords[srcn * 3 + 1];
                    csz[jj] = coords[srcn * 3 + 2];
                }
            }
            if (ng > 1) {
#pragma unroll
                for (int jj = 0; jj < 4; jj++) {
                    int e = r0 + 4 + jj; if (e > r1 - 1) e = r1 - 1;
                    nei[jj] = eidx[e];
                }
#pragma unroll
                for (int jj = 0; jj < 4; jj++) nsi[jj] = esrc[nei[jj]];
            }

            for (int g = 0; g < ng; g++) {
                if (l < 16) {
                    float r4[4];
#pragma unroll
                    for (int jj = 0; jj < 4; jj++) {
                        float dx = csx[jj] - cdx, dy = csy[jj] - cdy, dz = csz[jj] - cdz;
                        float dist = sqrtf(dx * dx + dy * dy + dz * dz + 1e-12f);
                        float u = (dist - (float)l * (1.0f / 3.0f)) * 3.2f;
                        r4[jj] = __expf(-u * u);
                    }
                    sE[w][0][l] = pack2(efd[0], efd[1]);
                    sE[w][1][l] = pack2(efd[2], efd[3]);
                    sR[w][0][l] = pack2(r4[0], r4[1]);
                    sR[w][1][l] = pack2(r4[2], r4[3]);
                }
                __syncwarp();
                if (g + 1 < ng) {
#pragma unroll
                    for (int jj = 0; jj < 4; jj++) {
                        efd[jj] = (l < DE) ? ef[nei[jj] * DE + l] : 0.f;
                        csx[jj] = coords[nsi[jj] * 3 + 0];
                        csy[jj] = coords[nsi[jj] * 3 + 1];
                        csz[jj] = coords[nsi[jj] * 3 + 2];
                    }
                }
                if (g + 2 < ng) {
#pragma unroll
                    for (int jj = 0; jj < 4; jj++) {
                        int e = r0 + (g + 2) * 4 + jj; if (e > r1 - 1) e = r1 - 1;
                        nei[jj] = eidx[e];
                    }
#pragma unroll
                    for (int jj = 0; jj < 4; jj++) nsi[jj] = esrc[nei[jj]];
                }
                ull paA[7], paB[7];
#pragma unroll
                for (int i = 0; i < 7; i++) { paA[i] = 0ull; paB[i] = 0ull; }
#pragma unroll 4
                for (int j = 0; j < 16; j++) {
                    ull xeA = sE[w][0][j], xeB = sE[w][1][j];
                    ull xrA = sR[w][0][j], xrB = sR[w][1][j];
                    ull x3A = e3 ? xeA : xrA;
                    ull x3B = e3 ? xeB : xrB;
                    const float* wr = &sWall[j][l];
                    { float wv = wr[0];   ull w2 = pack2(wv, wv); paA[0] = fma2(xeA, w2, paA[0]); paB[0] = fma2(xeB, w2, paB[0]); }
                    { float wv = wr[32];  ull w2 = pack2(wv, wv); paA[1] = fma2(xeA, w2, paA[1]); paB[1] = fma2(xeB, w2, paB[1]); }
                    { float wv = wr[64];  ull w2 = pack2(wv, wv); paA[2] = fma2(xeA, w2, paA[2]); paB[2] = fma2(xeB, w2, paB[2]); }
                    { float wv = wr[96];  ull w2 = pack2(wv, wv); paA[3] = fma2(x3A, w2, paA[3]); paB[3] = fma2(x3B, w2, paB[3]); }
                    { float wv = wr[128]; ull w2 = pack2(wv, wv); paA[4] = fma2(xrA, w2, paA[4]); paB[4] = fma2(xrB, w2, paB[4]); }
                    { float wv = wr[160]; ull w2 = pack2(wv, wv); paA[5] = fma2(xrA, w2, paA[5]); paB[5] = fma2(xrB, w2, paB[5]); }
                    { float wv = wr[192]; ull w2 = pack2(wv, wv); paA[6] = fma2(xrA, w2, paA[6]); paB[6] = fma2(xrB, w2, paB[6]); }
                }
                float v0[7], v1[7], v2[7], v3[7];
                float s0 = 0.f, s1v = 0.f, s2v = 0.f, s3 = 0.f;
                float q0 = 0.f, q1 = 0.f, q2 = 0.f, q3 = 0.f;
#pragma unroll
                for (int i = 0; i < 7; i++) {
                    float2 fa = unp2(paA[i]);
                    float2 fb = unp2(paB[i]);
                    float a0 = fmaxf(fa.x + bias[i], 0.f);
                    float a1 = fmaxf(fa.y + bias[i], 0.f);
                    float a2 = fmaxf(fb.x + bias[i], 0.f);
                    float a3 = fmaxf(fb.y + bias[i], 0.f);
                    v0[i] = a0; v1[i] = a1; v2[i] = a2; v3[i] = a3;
                    s0 += a0; s1v += a1; s2v += a2; s3 += a3;
                    q0 = fmaf(a0, a0, q0); q1 = fmaf(a1, a1, q1);
                    q2 = fmaf(a2, a2, q2); q3 = fmaf(a3, a3, q3);
                }
#pragma unroll
                for (int o = 16; o > 0; o >>= 1) {
                    s0 += __shfl_xor_sync(0xffffffffu, s0, o);
                    s1v += __shfl_xor_sync(0xffffffffu, s1v, o);
                    s2v += __shfl_xor_sync(0xffffffffu, s2v, o);
                    s3 += __shfl_xor_sync(0xffffffffu, s3, o);
                    q0 += __shfl_xor_sync(0xffffffffu, q0, o);
                    q1 += __shfl_xor_sync(0xffffffffu, q1, o);
                    q2 += __shfl_xor_sync(0xffffffffu, q2, o);
                    q3 += __shfl_xor_sync(0xffffffffu, q3, o);
                }
                int base = (g << 2);
                float m, var;
                m = s0 * 0.005f; var = q0 * 0.005f - m * m;
                float rs0 = (base + 0 < deg) ? rsqrtf(var + 1e-5f) : 0.f;
                sumMRS = fmaf(m, rs0, sumMRS);
                m = s1v * 0.005f; var = q1 * 0.005f - m * m;
                float rs1 = (base + 1 < deg) ? rsqrtf(var + 1e-5f) : 0.f;
                sumMRS = fmaf(m, rs1, sumMRS);
                m = s2v * 0.005f; var = q2 * 0.005f - m * m;
                float rs2 = (base + 2 < deg) ? rsqrtf(var + 1e-5f) : 0.f;
                sumMRS = fmaf(m, rs2, sumMRS);
                m = s3 * 0.005f; var = q3 * 0.005f - m * m;
                float rs3 = (base + 3 < deg) ? rsqrtf(var + 1e-5f) : 0.f;
                sumMRS = fmaf(m, rs3, sumMRS);
#pragma unroll
                for (int i = 0; i < 7; i++) {
                    float ta = TA[i];
                    ta = fmaf(v0[i], rs0, ta);
                    ta = fmaf(v1[i], rs1, ta);
                    ta = fmaf(v2[i], rs2, ta);
                    ta = fmaf(v3[i], rs3, ta);
                    TA[i] = ta;
                }
                __syncwarp();
            }
        }
        g_deg[side][node] = deg > 199 ? 199 : deg;
        float degf = (float)deg;
#pragma unroll
        for (int i = 0; i < 7; i++) {
            int k = l + 32 * i;
            if (k < DH) {
                float hv = h[node * DH + k];
                h[node * DH + k] = hv + lg[i] * (TA[i] - sumMRS) + degf * lb[i];
            }
        }
    }
}

// ---------------- fused attn: ATM=32 for 2 blocks/SM, all-tensor ----------------
#define ATM 32
#define ATK 64
#define QSTR 204
#define SSTR 68

__global__ void __launch_bounds__(256, 2) k_attn(const float* __restrict__ Wd,
                                                 const float* __restrict__ dtab) {
    extern __shared__ float sm[];
    float* sQ = sm;                       // 32*QSTR (h rows)
    float* sK = sQ + ATM * QSTR;          // 64*QSTR (KV tile; c rows 0..31 after loop)
    float* sS = sK + ATK * QSTR;          // 32*SSTR (P; epilogue scratch)
    float* sM = sS + ATM * SSTR;
    float* sL = sM + ATM;
    float* sC = sL + ATM;

    int side = blockIdx.z, b = blockIdx.y, qx = blockIdx.x;
    const float* Q  = g_h[side];
    const float* KV = g_h[side ^ 1];
    int t = threadIdx.x, w = t >> 5, l = t & 31;
    int q0 = qx * ATM;
    const float* Qb = Q + (b * NNODES + q0) * DH;
    const float* Kb = KV + b * NNODES * DH;

    for (int i = t; i < ATM * 100; i += 256) {
        int r = i / 100, p = i % 100;
        *reinterpret_cast<float2*>(&sQ[r * QSTR + 2 * p]) =
            reinterpret_cast<const float2*>(Qb)[r * 100 + p];
    }
    if (t < ATM) { sM[t] = -1e30f; sL[t] = 0.f; }
    __syncthreads();

    // warp tiling: mb = m-block (16 rows, 2 total), nh = n-quarter (0..3)
    int mb = w & 1, nh = w >> 1;
    int ar = l >> 2, ac = l & 3;
    int rlo = 16 * mb + ar, rhi = rlo + 8;
    const float* Aq = sQ + rlo * QSTR;
    // 25 nb-blocks of 8 output dims split 7/6/6/6 across nh
    int base_nb = nh ? (7 + 6 * (nh - 1)) : 0;
    int NB = nh ? 6 : 7;

    float po[7][4];
#pragma unroll
    for (int nb = 0; nb < 7; nb++)
#pragma unroll
        for (int i = 0; i < 4; i++) po[nb][i] = 0.f;

    for (int kt = 0; kt < NNODES / ATK; kt++) {
        for (int i = t; i < ATK * 100; i += 256) {
            int r = i / 100, p = i % 100;
            *reinterpret_cast<float2*>(&sK[r * QSTR + 2 * p]) =
                reinterpret_cast<const float2*>(Kb)[(kt * ATK + r) * 100 + p];
        }
        __syncthreads();

        // S = Q K^T : warp covers rows 16mb..+15, cols 16nh..+15
        float df[2][4];
#pragma unroll
        for (int nt = 0; nt < 2; nt++)
#pragma unroll
            for (int i = 0; i < 4; i++) df[nt][i] = 0.f;
#pragma unroll 5
        for (int k8 = 0; k8 < 25; k8++) {
            int k0 = k8 * 8;
            uint a0 = __float_as_uint(Aq[k0 + ac]);
            uint a1 = __float_as_uint(Aq[8 * QSTR + k0 + ac]);
            uint a2 = __float_as_uint(Aq[k0 + ac + 4]);
            uint a3 = __float_as_uint(Aq[8 * QSTR + k0 + ac + 4]);
#pragma unroll
            for (int nt = 0; nt < 2; nt++) {
                const float* Bk = sK + (16 * nh + 8 * nt + ar) * QSTR + k0;
                uint b0 = __float_as_uint(Bk[ac]);
                uint b1 = __float_as_uint(Bk[ac + 4]);
                mma_tf32(df[nt], a0, a1, a2, a3, b0, b1);
            }
        }
#pragma unroll
        for (int nt = 0; nt < 2; nt++) {
            int col = 16 * nh + 8 * nt + 2 * ac;
            sS[rlo * SSTR + col]       = df[nt][0] * TSCALE;
            sS[rlo * SSTR + col + 1]   = df[nt][1] * TSCALE;
            sS[rhi * SSTR + col]       = df[nt][2] * TSCALE;
            sS[rhi * SSTR + col + 1]   = df[nt][3] * TSCALE;
        }
        __syncthreads();

        // online softmax: 32 rows x 64 cols, 8 threads per row
        {
            int r = t / 8, part = t % 8;
            float mx = -1e30f;
            for (int c = part * 8; c < part * 8 + 8; c++)
                mx = fmaxf(mx, sS[r * SSTR + c]);
            mx = fmaxf(mx, __shfl_xor_sync(0xffffffffu, mx, 1));
            mx = fmaxf(mx, __shfl_xor_sync(0xffffffffu, mx, 2));
            mx = fmaxf(mx, __shfl_xor_sync(0xffffffffu, mx, 4));
            float m_old = sM[r];
            float m_new = fmaxf(m_old, mx);
            float lsum = 0.f;
            for (int c = part * 8; c < part * 8 + 8; c++) {
                float p = __expf(sS[r * SSTR + c] - m_new);
                sS[r * SSTR + c] = p;
                lsum += p;
            }
            lsum += __shfl_xor_sync(0xffffffffu, lsum, 1);
            lsum += __shfl_xor_sync(0xffffffffu, lsum, 2);
            lsum += __shfl_xor_sync(0xffffffffu, lsum, 4);
            if (part == 0) {
                float corr = __expf(m_old - m_new);
                sC[r] = corr;
                sL[r] = sL[r] * corr + lsum;
                sM[r] = m_new;
            }
        }
        __syncthreads();

        // rescale + PV (B-split compensated)
        {
            float clo = sC[rlo], chi = sC[rhi];
#pragma unroll
            for (int nb = 0; nb < 7; nb++) {
                po[nb][0] *= clo; po[nb][1] *= clo;
                po[nb][2] *= chi; po[nb][3] *= chi;
            }
#pragma unroll
            for (int k8 = 0; k8 < 8; k8++) {
                int k0 = k8 * 8;
                uint a0 = __float_as_uint(sS[rlo * SSTR + k0 + ac]);
                uint a1 = __float_as_uint(sS[rhi * SSTR + k0 + ac]);
                uint a2 = __float_as_uint(sS[rlo * SSTR + k0 + ac + 4]);
                uint a3 = __float_as_uint(sS[rhi * SSTR + k0 + ac + 4]);
#pragma unroll
                for (int nb = 0; nb < 7; nb++) {
                    if (nb >= NB) continue;
                    int d0 = (base_nb + nb) * 8;
                    uint b0h, b0l, b1h, b1l;
                    bsplit(sK[(k0 + ac) * QSTR + d0 + ar], b0h, b0l);
                    bsplit(sK[(k0 + ac + 4) * QSTR + d0 + ar], b1h, b1l);
                    mma_tf32(po[nb], a0, a1, a2, a3, b0h, b1h);
                    mma_tf32(po[nb], a0, a1, a2, a3, b0l, b1l);
                }
            }
        }
        __syncthreads();
    }

    // normalized c -> sK rows 0..31
    {
        float ilo = 1.0f / sL[rlo], ihi = 1.0f / sL[rhi];
#pragma unroll
        for (int nb = 0; nb < 7; nb++) {
            if (nb >= NB) continue;
            int c0 = (base_nb + nb) * 8 + 2 * ac;
            sK[rlo * QSTR + c0]     = po[nb][0] * ilo;
            sK[rlo * QSTR + c0 + 1] = po[nb][1] * ilo;
            sK[rhi * QSTR + c0]     = po[nb][2] * ihi;
            sK[rhi * QSTR + c0 + 1] = po[nb][3] * ihi;
        }
    }
    __syncthreads();

    // down-proj: A = [h||c], B = Wd (B-split compensated, direct from global)
    float da[7][4];
#pragma unroll
    for (int nb = 0; nb < 7; nb++)
#pragma unroll
        for (int i = 0; i < 4; i++) da[nb][i] = 0.f;

#pragma unroll 2
    for (int kb = 0; kb < 50; kb++) {
        const float* Asrc = (kb < 25) ? sQ : sK;
        int k0 = (kb < 25) ? 8 * kb : 8 * (kb - 25);
        uint a0 = __float_as_uint(Asrc[rlo * QSTR + k0 + ac]);
        uint a1 = __float_as_uint(Asrc[rhi * QSTR + k0 + ac]);
        uint a2 = __float_as_uint(Asrc[rlo * QSTR + k0 + ac + 4]);
        uint a3 = __float_as_uint(Asrc[rhi * QSTR + k0 + ac + 4]);
        int kg = 8 * kb;
#pragma unroll
        for (int nb = 0; nb < 7; nb++) {
            if (nb >= NB) continue;
            int d0 = (base_nb + nb) * 8;
            uint b0h, b0l, b1h, b1l;
            bsplit(Wd[(kg + ac) * DH + d0 + ar], b0h, b0l);
            bsplit(Wd[(kg + ac + 4) * DH + d0 + ar], b1h, b1l);
            mma_tf32(da[nb], a0, a1, a2, a3, b0h, b1h);
            mma_tf32(da[nb], a0, a1, a2, a3, b0l, b1l);
        }
    }

    // epilogue: relu + dtab[deg], row-reduce, column sums
    {
        int dg_lo = g_deg[side][b * NNODES + q0 + rlo];
        int dg_hi = g_deg[side][b * NNODES + q0 + rhi];
#pragma unroll
        for (int nb = 0; nb < 7; nb++) {
            if (nb >= NB) continue;
            int c0 = (base_nb + nb) * 8 + 2 * ac;
            float v0 = fmaxf(da[nb][0], 0.f) + dtab[dg_lo * DH + c0];
            float v1 = fmaxf(da[nb][1], 0.f) + dtab[dg_lo * DH + c0 + 1];
            float v2 = fmaxf(da[nb][2], 0.f) + dtab[dg_hi * DH + c0];
            float v3 = fmaxf(da[nb][3], 0.f) + dtab[dg_hi * DH + c0 + 1];
            float s0 = v0 + v2, s1 = v1 + v3;
            s0 += __shfl_xor_sync(0xffffffffu, s0, 4);
            s1 += __shfl_xor_sync(0xffffffffu, s1, 4);
            s0 += __shfl_xor_sync(0xffffffffu, s0, 8);
            s1 += __shfl_xor_sync(0xffffffffu, s1, 8);
            s0 += __shfl_xor_sync(0xffffffffu, s0, 16);
            s1 += __shfl_xor_sync(0xffffffffu, s1, 16);
            if (l < 4) {
                int cc = (base_nb + nb) * 8 + 2 * l;
                sS[mb * 208 + cc] = s0;
                sS[mb * 208 + cc + 1] = s1;
            }
        }
    }
    __syncthreads();
    if (t < DH) {
        float s = sS[t] + sS[208 + t];
        g_part[side][b][qx][t] = s;
    }
}

// ---------------- fused readout ----------------
__global__ void __launch_bounds__(256) k_readout(
        const float* __restrict__ i1, const float* __restrict__ i2,
        const float* __restrict__ W1, const float* __restrict__ b1,
        const float* __restrict__ W2, const float* __restrict__ b2,
        const float* __restrict__ W3, const float* __restrict__ b3,
        const float* __restrict__ W4, const float* __restrict__ b4,
        float* __restrict__ out) {
    __shared__ float sx[618], s1[400], s2[200], s3[104];
    int b = blockIdx.x, t = threadIdx.x;
    if (t < DH) {
        float m1 = 0.f, m2 = 0.f;
#pragma unroll
        for (int tile = 0; tile < 16; tile++) {
            m1 += g_part[0][b][tile][t];
            m2 += g_part[1][b][tile][t];
        }
        m1 *= (1.0f / NNODES); m2 *= (1.0f / NNODES);
        sx[t] = m1; sx[206 + t] = m2; sx[412 + t] = m1 - m2;
    } else if (t < DH + DI) {
        int j = t - DH;
        float m1 = 0.f, m2 = 0.f;
#pragma unroll 4
        for (int n = 0; n < NNODES; n++) {
            m1 += i1[(b * NNODES + n) * DI + j];
            m2 += i2[(b * NNODES + n) * DI + j];
        }
        m1 *= (1.0f / NNODES); m2 *= (1.0f / NNODES);
        sx[200 + j] = m1; sx[406 + j] = m2; sx[612 + j] = m1 - m2;
    }
    __syncthreads();
    for (int o = t; o < 400; o += 256) {
        float a = b1[o];
        for (int j = 0; j < 618; j++) a = fmaf(sx[j], W1[j * 400 + o], a);
        s1[o] = fmaxf(a, 0.f);
    }
    __syncthreads();
    for (int o = t; o < 200; o += 256) {
        float a = b2[o];
        for (int j = 0; j < 400; j++) a = fmaf(s1[j], W2[j * 200 + o], a);
        s2[o] = fmaxf(a, 0.f);
    }
    __syncthreads();
    for (int o = t; o < 100; o += 256) {
        float a = b3[o];
        for (int j = 0; j < 200; j++) a = fmaf(s2[j], W3[j * 100 + o], a);
        s3[o] = fmaxf(a, 0.f);
    }
    __syncthreads();
    if (t < 32) {
        float a = 0.f;
        for (int j = t; j < 100; j += 32) a = fmaf(s3[j], W4[j], a);
#pragma unroll
        for (int o = 16; o > 0; o >>= 1) a += __shfl_xor_sync(0xffffffffu, a, o);
        if (t == 0) out[b] = a + b4[0];
    }
}

// ---------------- launch ----------------
extern "C" void kernel_launch(void* const* d_in, const int* in_sizes, int n_in,
                              void* d_out, int out_size) {
    const float* atom1  = (const float*)d_in[0];
    const float* atom2  = (const float*)d_in[1];
    const float* coords1 = (const float*)d_in[2];
    const float* coords2 = (const float*)d_in[3];
    const float* ef1    = (const float*)d_in[4];
    const float* ef2    = (const float*)d_in[5];
    const float* int1   = (const float*)d_in[6];
    const float* int2   = (const float*)d_in[7];
    const int*   src1   = (const int*)d_in[8];
    const int*   dst1   = (const int*)d_in[9];
    const int*   src2   = (const int*)d_in[10];
    const int*   dst2   = (const int*)d_in[11];
    const float* W_atom = (const float*)d_in[12];
    const float* W_edge = (const float*)d_in[13];
    const float* W_rbf  = (const float*)d_in[14];
    const float* b_rbf  = (const float*)d_in[15];
    const float* ln_g   = (const float*)d_in[16];
    const float* ln_b   = (const float*)d_in[17];
    const float* W_down = (const float*)d_in[18];
    const float* dtab   = (const float*)d_in[19];
    const float* W_f1   = (const float*)d_in[20];
    const float* b_f1   = (const float*)d_in[21];
    const float* W_f2   = (const float*)d_in[22];
    const float* b_f2   = (const float*)d_in[23];
    const float* W_f3   = (const float*)d_in[24];
    const float* b_f3   = (const float*)d_in[25];
    const float* W_f4   = (const float*)d_in[26];
    const float* b_f4   = (const float*)d_in[27];
    float* out = (float*)d_out;

    const int SMEM_ATOM = (DA * DH + 8 * 2 * DA) * 4;
    const int SMEM_ATTN = (ATM * QSTR + ATK * QSTR + ATM * SSTR + 3 * ATM) * 4;  // 87424

    cudaFuncSetAttribute(k_atom, cudaFuncAttributeMaxDynamicSharedMemorySize, SMEM_ATOM);
    cudaFuncSetAttribute(k_attn, cudaFuncAttributeMaxDynamicSharedMemorySize, SMEM_ATTN);

    dim3 gatom(1024, 2);
    k_atom<<<gatom, 256, SMEM_ATOM>>>(atom1, atom2, dst1, dst2, W_atom, ln_g, ln_b);
    k_scanfill<<<1026, 1024>>>(dst1, dst2);
    dim3 ggath(1024, 2);
    k_gather<<<ggath, 128>>>(ef1, ef2, coords1, coords2, src1, src2,
                             W_edge, W_rbf, b_rbf, ln_g, ln_b);
    dim3 agrid(NNODES / ATM, BB, 2);
    k_attn<<<agrid, 256, SMEM_ATTN>>>(W_down, dtab);
    k_readout<<<BB, 256>>>(int1, int2, W_f1, b_f1, W_f2, b_f2,
                           W_f3, b_f3, W_f4, b_f4, out);
}

// round 11
// speedup vs baseline: 1.0893x; 1.0893x over previous
#include <cuda_runtime.h>
#include <math.h>

#define BB 64
#define NNODES 512
#define BN 32768
#define EE 524288
#define DA 70
#define DE 14
#define DH 200
#define DI 6
#define TSCALE 0.07071067811865475f

typedef unsigned long long ull;
typedef unsigned int uint;

__device__ __forceinline__ ull fma2(ull a, ull b, ull c) {
    ull d; asm("fma.rn.f32x2 %0, %1, %2, %3;" : "=l"(d) : "l"(a), "l"(b), "l"(c)); return d;
}
__device__ __forceinline__ ull pack2(float x, float y) {
    ull r; asm("mov.b64 %0, {%1, %2};" : "=l"(r) : "f"(x), "f"(y)); return r;
}
__device__ __forceinline__ float2 unp2(ull a) {
    float2 f; asm("mov.b64 {%0, %1}, %2;" : "=f"(f.x), "=f"(f.y) : "l"(a)); return f;
}
__device__ __forceinline__ ull ld2s(const float* p) { return *reinterpret_cast<const ull*>(p); }

__device__ __forceinline__ void mma_tf32(float* d, uint a0, uint a1, uint a2, uint a3,
                                         uint b0, uint b1) {
    asm volatile("mma.sync.aligned.m16n8k8.row.col.f32.tf32.tf32.f32 "
                 "{%0,%1,%2,%3}, {%4,%5,%6,%7}, {%8,%9}, {%0,%1,%2,%3};"
                 : "+f"(d[0]), "+f"(d[1]), "+f"(d[2]), "+f"(d[3])
                 : "r"(a0), "r"(a1), "r"(a2), "r"(a3), "r"(b0), "r"(b1));
}
__device__ __forceinline__ void bsplit(float b, uint& hi, uint& lo) {
    uint bb = __float_as_uint(b);
    hi = bb & 0xFFFFE000u;
    lo = __float_as_uint(b - __uint_as_float(hi));
}

__device__ float g_h[2][BN * DH];
__device__ int   g_deg[2][BN];
__device__ int   g_cnt[2][BN];
__device__ int   g_rowptr[2][BN + 1];
__device__ int   g_cursor[2][BN];
__device__ int   g_eidx[2][EE];
__device__ float g_part[2][BB][16][DH];
__device__ int   g_flag[2];

// ---------------- atom GEMM + LN + edge counting + flag reset ----------------
__global__ void __launch_bounds__(256) k_atom(const float* __restrict__ a1,
                                              const float* __restrict__ a2,
                                              const int* __restrict__ d1,
                                              const int* __restrict__ d2,
                                              const float* __restrict__ W,
                                              const float* __restrict__ lng,
                                              const float* __restrict__ lnb) {
    extern __shared__ float sm[];
    float* sW = sm;
    float* sA = sm + DA * DH;
    int side = blockIdx.y;
    const float* atom = side ? a2 : a1;
    const int* dst = side ? d2 : d1;
    float* out = g_h[side];
    int t = threadIdx.x;
    if (blockIdx.x == 0 && t == 0) g_flag[side] = 0;
    {
        int e0 = blockIdx.x * 256 + t;
#pragma unroll
        for (int r = 0; r < 2; r++) atomicAdd(&g_cnt[side][dst[e0 + r * 262144]], 1);
    }
    for (int i = t; i < DA * DH; i += 256) sW[i] = W[i];
    int w = t / 32, l = t % 32;
    float lg[7], lb[7];
#pragma unroll
    for (int i = 0; i < 7; i++) {
        int k = l + 32 * i;
        lg[i] = (k < DH) ? lng[k] : 0.f;
        lb[i] = (k < DH) ? lnb[k] : 0.f;
    }
    __syncthreads();
    float* myA = sA + w * 2 * DA;
    for (int pair = 0; pair < 2; pair++) {
        int n0 = (blockIdx.x * 8 + w) * 4 + pair * 2;
        for (int j = l; j < 2 * DA; j += 32) myA[j] = atom[n0 * DA + j];
        __syncwarp();
        float a0[7], a1v[7];
#pragma unroll
        for (int i = 0; i < 7; i++) { a0[i] = 0.f; a1v[i] = 0.f; }
        for (int j = 0; j < DA; j++) {
            float x0 = myA[j], x1 = myA[DA + j];
#pragma unroll
            for (int i = 0; i < 7; i++) {
                int k = l + 32 * i;
                if (k < DH) {
                    float wv = sW[j * DH + k];
                    a0[i] = fmaf(x0, wv, a0[i]);
                    a1v[i] = fmaf(x1, wv, a1v[i]);
                }
            }
        }
#pragma unroll
        for (int nn = 0; nn < 2; nn++) {
            float* acc = nn ? a1v : a0;
            float s = 0.f, s2v = 0.f;
#pragma unroll
            for (int i = 0; i < 7; i++) {
                int k = l + 32 * i;
                if (k < DH) { float v = fmaxf(acc[i], 0.f); acc[i] = v; s += v; s2v += v * v; }
            }
#pragma unroll
            for (int o = 16; o > 0; o >>= 1) {
                s += __shfl_xor_sync(0xffffffffu, s, o);
                s2v += __shfl_xor_sync(0xffffffffu, s2v, o);
            }
            float m = s * (1.0f / DH);
            float rs = rsqrtf(s2v * (1.0f / DH) - m * m + 1e-5f);
#pragma unroll
            for (int i = 0; i < 7; i++) {
                int k = l + 32 * i;
                if (k < DH) out[(n0 + nn) * DH + k] = lg[i] * (acc[i] - m) * rs + lb[i];
            }
        }
        __syncwarp();
    }
}

// ---------------- merged CSR scan + fill ----------------
__global__ void __launch_bounds__(1024) k_scanfill(const int* __restrict__ d1,
                                                   const int* __restrict__ d2) {
    int t = threadIdx.x;
    if (blockIdx.x < 2) {
        int side = blockIdx.x;
        __shared__ int ws[32];
        int base = t * 32;
        int loc[32];
        int sum = 0;
#pragma unroll
        for (int i = 0; i < 32; i++) { loc[i] = g_cnt[side][base + i]; sum += loc[i]; }
        int l = t & 31, w = t >> 5;
        int v = sum;
#pragma unroll
        for (int off = 1; off < 32; off <<= 1) {
            int n = __shfl_up_sync(0xffffffffu, v, off);
            if (l >= off) v += n;
        }
        if (l == 31) ws[w] = v;
        __syncthreads();
        if (w == 0) {
            int x = ws[l];
#pragma unroll
            for (int off = 1; off < 32; off <<= 1) {
                int n = __shfl_up_sync(0xffffffffu, x, off);
                if (l >= off) x += n;
            }
            ws[l] = x;
        }
        __syncthreads();
        int run = v - sum + (w > 0 ? ws[w - 1] : 0);
        for (int i = 0; i < 32; i++) {
            g_rowptr[side][base + i] = run;
            g_cursor[side][base + i] = run;
            run += loc[i];
        }
        if (t == 1023) g_rowptr[side][BN] = run;
        __threadfence();
        __syncthreads();
        if (t == 0) atomicExch(&g_flag[side], 1);
    } else {
        int fb = blockIdx.x - 2;
        int side = fb >> 9;
        int slice = fb & 511;
        const int* dst = side ? d2 : d1;
        if (t == 0) { while (atomicAdd(&g_flag[side], 0) == 0) __nanosleep(128); }
        __syncthreads();
        int e = slice * 1024 + t;
        int slot = atomicAdd(&g_cursor[side][dst[e]], 1);
        g_eidx[side][slot] = e;
        if (t < 64) g_cnt[side][slice * 64 + t] = 0;
    }
}

// ---------------- edge gather: f32x2 packed over edges (R9 config) ----------------
__global__ void __launch_bounds__(128, 4) k_gather(
        const float* __restrict__ ef1, const float* __restrict__ ef2,
        const float* __restrict__ co1, const float* __restrict__ co2,
        const int* __restrict__ s1, const int* __restrict__ s2,
        const float* __restrict__ W_edge, const float* __restrict__ W_rbf,
        const float* __restrict__ b_rbf,
        const float* __restrict__ lng, const float* __restrict__ lnb) {
    __shared__ float sWall[16][224];
    __shared__ __align__(16) ull sE[4][2][16];
    __shared__ __align__(16) ull sR[4][2][16];

    int side = blockIdx.y;
    const float* ef     = side ? ef2 : ef1;
    const float* coords = side ? co2 : co1;
    const int*   esrc   = side ? s2 : s1;
    const int*   eidx   = g_eidx[side];
    const int*   rowptr = g_rowptr[side];
    float* h = g_h[side];
    int t = threadIdx.x, w = t >> 5, l = t & 31;

    for (int idx = t; idx < 16 * 224; idx += 128) {
        int j = idx / 224, k = idx % 224;
        float v = 0.f;
        if (k < 100) { if (j < DE) v = W_edge[j * 100 + k]; }
        else if (k < 200) v = W_rbf[j * 100 + (k - 100)];
        sWall[j][k] = v;
    }
    float bias[7], lg[7], lb[7];
#pragma unroll
    for (int i = 0; i < 7; i++) {
        int k = l + 32 * i;
        bias[i] = (k >= 100 && k < 200) ? b_rbf[k - 100] : 0.f;
        lg[i] = (k < DH) ? lng[k] : 0.f;
        lb[i] = (k < DH) ? lnb[k] : 0.f;
    }
    bool e3 = (l < 4);
    __syncthreads();

    int wg = blockIdx.x * 4 + w;
    int nw = gridDim.x * 4;
    for (int node = wg; node < BN; node += nw) {
        int r0 = rowptr[node], r1 = rowptr[node + 1];
        int deg = r1 - r0;
        float TA[7];
#pragma unroll
        for (int i = 0; i < 7; i++) TA[i] = 0.f;
        float sumMRS = 0.f;

        if (deg > 0) {
            float cdx = coords[node * 3 + 0];
            float cdy = coords[node * 3 + 1];
            float cdz = coords[node * 3 + 2];
            int ng = (deg + 3) >> 2;
            int nei[4], nsi[4];
            float efd[4], csx[4], csy[4], csz[4];
            {
                int ei0[4];
#pragma unroll
                for (int jj = 0; jj < 4; jj++) {
                    int e = r0 + jj; if (e > r1 - 1) e = r1 - 1;
                    ei0[jj] = eidx[e];
                }
#pragma unroll
                for (int jj = 0; jj < 4; jj++) {
                    int srcn = esrc[ei0[jj]];
                    efd[jj] = (l < DE) ? ef[ei0[jj] * DE + l] : 0.f;
                    csx[jj] = coords[srcn * 3 + 0];
                    csy[jj] = coords[srcn * 3 + 1];
                    csz[jj] = coords[srcn * 3 + 2];
                }
            }
            if (ng > 1) {
#pragma unroll
                for (int jj = 0; jj < 4; jj++) {
                    int e = r0 + 4 + jj; if (e > r1 - 1) e = r1 - 1;
                    nei[jj] = eidx[e];
                }
#pragma unroll
                for (int jj = 0; jj < 4; jj++) nsi[jj] = esrc[nei[jj]];
            }

            for (int g = 0; g < ng; g++) {
                if (l < 16) {
                    float r4[4];
#pragma unroll
                    for (int jj = 0; jj < 4; jj++) {
                        float dx = csx[jj] - cdx, dy = csy[jj] - cdy, dz = csz[jj] - cdz;
                        float dist = sqrtf(dx * dx + dy * dy + dz * dz + 1e-12f);
                        float u = (dist - (float)l * (1.0f / 3.0f)) * 3.2f;
                        r4[jj] = __expf(-u * u);
                    }
                    sE[w][0][l] = pack2(efd[0], efd[1]);
                    sE[w][1][l] = pack2(efd[2], efd[3]);
                    sR[w][0][l] = pack2(r4[0], r4[1]);
                    sR[w][1][l] = pack2(r4[2], r4[3]);
                }
                __syncwarp();
                if (g + 1 < ng) {
#pragma unroll
                    for (int jj = 0; jj < 4; jj++) {
                        efd[jj] = (l < DE) ? ef[nei[jj] * DE + l] : 0.f;
                        csx[jj] = coords[nsi[jj] * 3 + 0];
                        csy[jj] = coords[nsi[jj] * 3 + 1];
                        csz[jj] = coords[nsi[jj] * 3 + 2];
                    }
                }
                if (g + 2 < ng) {
#pragma unroll
                    for (int jj = 0; jj < 4; jj++) {
                        int e = r0 + (g + 2) * 4 + jj; if (e > r1 - 1) e = r1 - 1;
                        nei[jj] = eidx[e];
                    }
#pragma unroll
                    for (int jj = 0; jj < 4; jj++) nsi[jj] = esrc[nei[jj]];
                }
                ull paA[7], paB[7];
#pragma unroll
                for (int i = 0; i < 7; i++) { paA[i] = 0ull; paB[i] = 0ull; }
#pragma unroll 4
                for (int j = 0; j < 16; j++) {
                    ull xeA = sE[w][0][j], xeB = sE[w][1][j];
                    ull xrA = sR[w][0][j], xrB = sR[w][1][j];
                    ull x3A = e3 ? xeA : xrA;
                    ull x3B = e3 ? xeB : xrB;
                    const float* wr = &sWall[j][l];
                    { float wv = wr[0];   ull w2 = pack2(wv, wv); paA[0] = fma2(xeA, w2, paA[0]); paB[0] = fma2(xeB, w2, paB[0]); }
                    { float wv = wr[32];  ull w2 = pack2(wv, wv); paA[1] = fma2(xeA, w2, paA[1]); paB[1] = fma2(xeB, w2, paB[1]); }
                    { float wv = wr[64];  ull w2 = pack2(wv, wv); paA[2] = fma2(xeA, w2, paA[2]); paB[2] = fma2(xeB, w2, paB[2]); }
                    { float wv = wr[96];  ull w2 = pack2(wv, wv); paA[3] = fma2(x3A, w2, paA[3]); paB[3] = fma2(x3B, w2, paB[3]); }
                    { float wv = wr[128]; ull w2 = pack2(wv, wv); paA[4] = fma2(xrA, w2, paA[4]); paB[4] = fma2(xrB, w2, paB[4]); }
                    { float wv = wr[160]; ull w2 = pack2(wv, wv); paA[5] = fma2(xrA, w2, paA[5]); paB[5] = fma2(xrB, w2, paB[5]); }
                    { float wv = wr[192]; ull w2 = pack2(wv, wv); paA[6] = fma2(xrA, w2, paA[6]); paB[6] = fma2(xrB, w2, paB[6]); }
                }
                float v0[7], v1[7], v2[7], v3[7];
                float s0 = 0.f, s1v = 0.f, s2v = 0.f, s3 = 0.f;
                float q0 = 0.f, q1 = 0.f, q2 = 0.f, q3 = 0.f;
#pragma unroll
                for (int i = 0; i < 7; i++) {
                    float2 fa = unp2(paA[i]);
                    float2 fb = unp2(paB[i]);
                    float a0 = fmaxf(fa.x + bias[i], 0.f);
                    float a1 = fmaxf(fa.y + bias[i], 0.f);
                    float a2 = fmaxf(fb.x + bias[i], 0.f);
                    float a3 = fmaxf(fb.y + bias[i], 0.f);
                    v0[i] = a0; v1[i] = a1; v2[i] = a2; v3[i] = a3;
                    s0 += a0; s1v += a1; s2v += a2; s3 += a3;
                    q0 = fmaf(a0, a0, q0); q1 = fmaf(a1, a1, q1);
                    q2 = fmaf(a2, a2, q2); q3 = fmaf(a3, a3, q3);
                }
#pragma unroll
                for (int o = 16; o > 0; o >>= 1) {
                    s0 += __shfl_xor_sync(0xffffffffu, s0, o);
                    s1v += __shfl_xor_sync(0xffffffffu, s1v, o);
                    s2v += __shfl_xor_sync(0xffffffffu, s2v, o);
                    s3 += __shfl_xor_sync(0xffffffffu, s3, o);
                    q0 += __shfl_xor_sync(0xffffffffu, q0, o);
                    q1 += __shfl_xor_sync(0xffffffffu, q1, o);
                    q2 += __shfl_xor_sync(0xffffffffu, q2, o);
                    q3 += __shfl_xor_sync(0xffffffffu, q3, o);
                }
                int base = (g << 2);
                float m, var;
                m = s0 * 0.005f; var = q0 * 0.005f - m * m;
                float rs0 = (base + 0 < deg) ? rsqrtf(var + 1e-5f) : 0.f;
                sumMRS = fmaf(m, rs0, sumMRS);
                m = s1v * 0.005f; var = q1 * 0.005f - m * m;
                float rs1 = (base + 1 < deg) ? rsqrtf(var + 1e-5f) : 0.f;
                sumMRS = fmaf(m, rs1, sumMRS);
                m = s2v * 0.005f; var = q2 * 0.005f - m * m;
                float rs2 = (base + 2 < deg) ? rsqrtf(var + 1e-5f) : 0.f;
                sumMRS = fmaf(m, rs2, sumMRS);
                m = s3 * 0.005f; var = q3 * 0.005f - m * m;
                float rs3 = (base + 3 < deg) ? rsqrtf(var + 1e-5f) : 0.f;
                sumMRS = fmaf(m, rs3, sumMRS);
#pragma unroll
                for (int i = 0; i < 7; i++) {
                    float ta = TA[i];
                    ta = fmaf(v0[i], rs0, ta);
                    ta = fmaf(v1[i], rs1, ta);
                    ta = fmaf(v2[i], rs2, ta);
                    ta = fmaf(v3[i], rs3, ta);
                    TA[i] = ta;
                }
                __syncwarp();
            }
        }
        g_deg[side][node] = deg > 199 ? 199 : deg;
        float degf = (float)deg;
#pragma unroll
        for (int i = 0; i < 7; i++) {
            int k = l + 32 * i;
            if (k < DH) {
                float hv = h[node * DH + k];
                h[node * DH + k] = hv + lg[i] * (TA[i] - sumMRS) + degf * lb[i];
            }
        }
    }
}

// ---------------- fused attn: ATM=32, 2 blocks/SM, float4 tile loads ----------------
#define ATM 32
#define ATK 64
#define QSTR 204
#define SSTR 68

__global__ void __launch_bounds__(256, 2) k_attn(const float* __restrict__ Wd,
                                                 const float* __restrict__ dtab) {
    extern __shared__ float sm[];
    float* sQ = sm;                       // 32*QSTR (h rows)
    float* sK = sQ + ATM * QSTR;          // 64*QSTR (KV tile; c rows 0..31 after loop)
    float* sS = sK + ATK * QSTR;          // 32*SSTR (P; epilogue scratch)
    float* sM = sS + ATM * SSTR;
    float* sL = sM + ATM;
    float* sC = sL + ATM;

    int side = blockIdx.z, b = blockIdx.y, qx = blockIdx.x;
    const float* Q  = g_h[side];
    const float* KV = g_h[side ^ 1];
    int t = threadIdx.x, w = t >> 5, l = t & 31;
    int q0 = qx * ATM;
    const float* Qb = Q + (b * NNODES + q0) * DH;
    const float* Kb = KV + b * NNODES * DH;

    // float4 loads: row = 50 float4 (800B, 16B-aligned); smem stride 204*4=816B (16B-aligned)
    for (int i = t; i < ATM * 50; i += 256) {
        int r = i / 50, p = i % 50;
        *reinterpret_cast<float4*>(&sQ[r * QSTR + 4 * p]) =
            reinterpret_cast<const float4*>(Qb)[r * 50 + p];
    }
    if (t < ATM) { sM[t] = -1e30f; sL[t] = 0.f; }
    __syncthreads();

    int mb = w & 1, nh = w >> 1;
    int ar = l >> 2, ac = l & 3;
    int rlo = 16 * mb + ar, rhi = rlo + 8;
    const float* Aq = sQ + rlo * QSTR;
    int base_nb = nh ? (7 + 6 * (nh - 1)) : 0;
    int NB = nh ? 6 : 7;

    float po[7][4];
#pragma unroll
    for (int nb = 0; nb < 7; nb++)
#pragma unroll
        for (int i = 0; i < 4; i++) po[nb][i] = 0.f;

    for (int kt = 0; kt < NNODES / ATK; kt++) {
        for (int i = t; i < ATK * 50; i += 256) {
            int r = i / 50, p = i % 50;
            *reinterpret_cast<float4*>(&sK[r * QSTR + 4 * p]) =
                reinterpret_cast<const float4*>(Kb)[(kt * ATK + r) * 50 + p];
        }
        __syncthreads();

        // S = Q K^T
        float df[2][4];
#pragma unroll
        for (int nt = 0; nt < 2; nt++)
#pragma unroll
            for (int i = 0; i < 4; i++) df[nt][i] = 0.f;
#pragma unroll 5
        for (int k8 = 0; k8 < 25; k8++) {
            int k0 = k8 * 8;
            uint a0 = __float_as_uint(Aq[k0 + ac]);
            uint a1 = __float_as_uint(Aq[8 * QSTR + k0 + ac]);
            uint a2 = __float_as_uint(Aq[k0 + ac + 4]);
            uint a3 = __float_as_uint(Aq[8 * QSTR + k0 + ac + 4]);
#pragma unroll
            for (int nt = 0; nt < 2; nt++) {
                const float* Bk = sK + (16 * nh + 8 * nt + ar) * QSTR + k0;
                uint b0 = __float_as_uint(Bk[ac]);
                uint b1 = __float_as_uint(Bk[ac + 4]);
                mma_tf32(df[nt], a0, a1, a2, a3, b0, b1);
            }
        }
#pragma unroll
        for (int nt = 0; nt < 2; nt++) {
            int col = 16 * nh + 8 * nt + 2 * ac;
            sS[rlo * SSTR + col]       = df[nt][0] * TSCALE;
            sS[rlo * SSTR + col + 1]   = df[nt][1] * TSCALE;
            sS[rhi * SSTR + col]       = df[nt][2] * TSCALE;
            sS[rhi * SSTR + col + 1]   = df[nt][3] * TSCALE;
        }
        __syncthreads();

        // online softmax
        {
            int r = t / 8, part = t % 8;
            float mx = -1e30f;
            for (int c = part * 8; c < part * 8 + 8; c++)
                mx = fmaxf(mx, sS[r * SSTR + c]);
            mx = fmaxf(mx, __shfl_xor_sync(0xffffffffu, mx, 1));
            mx = fmaxf(mx, __shfl_xor_sync(0xffffffffu, mx, 2));
            mx = fmaxf(mx, __shfl_xor_sync(0xffffffffu, mx, 4));
            float m_old = sM[r];
            float m_new = fmaxf(m_old, mx);
            float lsum = 0.f;
            for (int c = part * 8; c < part * 8 + 8; c++) {
                float p = __expf(sS[r * SSTR + c] - m_new);
                sS[r * SSTR + c] = p;
                lsum += p;
            }
            lsum += __shfl_xor_sync(0xffffffffu, lsum, 1);
            lsum += __shfl_xor_sync(0xffffffffu, lsum, 2);
            lsum += __shfl_xor_sync(0xffffffffu, lsum, 4);
            if (part == 0) {
                float corr = __expf(m_old - m_new);
                sC[r] = corr;
                sL[r] = sL[r] * corr + lsum;
                sM[r] = m_new;
            }
        }
        __syncthreads();

        // rescale + PV (B-split compensated)
        {
            float clo = sC[rlo], chi = sC[rhi];
#pragma unroll
            for (int nb = 0; nb < 7; nb++) {
                po[nb][0] *= clo; po[nb][1] *= clo;
                po[nb][2] *= chi; po[nb][3] *= chi;
            }
#pragma unroll
            for (int k8 = 0; k8 < 8; k8++) {
                int k0 = k8 * 8;
                uint a0 = __float_as_uint(sS[rlo * SSTR + k0 + ac]);
                uint a1 = __float_as_uint(sS[rhi * SSTR + k0 + ac]);
                uint a2 = __float_as_uint(sS[rlo * SSTR + k0 + ac + 4]);
                uint a3 = __float_as_uint(sS[rhi * SSTR + k0 + ac + 4]);
#pragma unroll
                for (int nb = 0; nb < 7; nb++) {
                    if (nb >= NB) continue;
                    int d0 = (base_nb + nb) * 8;
                    uint b0h, b0l, b1h, b1l;
                    bsplit(sK[(k0 + ac) * QSTR + d0 + ar], b0h, b0l);
                    bsplit(sK[(k0 + ac + 4) * QSTR + d0 + ar], b1h, b1l);
                    mma_tf32(po[nb], a0, a1, a2, a3, b0h, b1h);
                    mma_tf32(po[nb], a0, a1, a2, a3, b0l, b1l);
                }
            }
        }
        __syncthreads();
    }

    // normalized c -> sK rows 0..31
    {
        float ilo = 1.0f / sL[rlo], ihi = 1.0f / sL[rhi];
#pragma unroll
        for (int nb = 0; nb < 7; nb++) {
            if (nb >= NB) continue;
            int c0 = (base_nb + nb) * 8 + 2 * ac;
            sK[rlo * QSTR + c0]     = po[nb][0] * ilo;
            sK[rlo * QSTR + c0 + 1] = po[nb][1] * ilo;
            sK[rhi * QSTR + c0]     = po[nb][2] * ihi;
            sK[rhi * QSTR + c0 + 1] = po[nb][3] * ihi;
        }
    }
    __syncthreads();

    // down-proj: A = [h||c], B = Wd (B-split compensated, direct from global)
    float da[7][4];
#pragma unroll
    for (int nb = 0; nb < 7; nb++)
#pragma unroll
        for (int i = 0; i < 4; i++) da[nb][i] = 0.f;

#pragma unroll 2
    for (int kb = 0; kb < 50; kb++) {
        const float* Asrc = (kb < 25) ? sQ : sK;
        int k0 = (kb < 25) ? 8 * kb : 8 * (kb - 25);
        uint a0 = __float_as_uint(Asrc[rlo * QSTR + k0 + ac]);
        uint a1 = __float_as_uint(Asrc[rhi * QSTR + k0 + ac]);
        uint a2 = __float_as_uint(Asrc[rlo * QSTR + k0 + ac + 4]);
        uint a3 = __float_as_uint(Asrc[rhi * QSTR + k0 + ac + 4]);
        int kg = 8 * kb;
#pragma unroll
        for (int nb = 0; nb < 7; nb++) {
            if (nb >= NB) continue;
            int d0 = (base_nb + nb) * 8;
            uint b0h, b0l, b1h, b1l;
            bsplit(Wd[(kg + ac) * DH + d0 + ar], b0h, b0l);
            bsplit(Wd[(kg + ac + 4) * DH + d0 + ar], b1h, b1l);
            mma_tf32(da[nb], a0, a1, a2, a3, b0h, b1h);
            mma_tf32(da[nb], a0, a1, a2, a3, b0l, b1l);
        }
    }

    // epilogue: relu + dtab[deg], row-reduce, column sums
    {
        int dg_lo = g_deg[side][b * NNODES + q0 + rlo];
        int dg_hi = g_deg[side][b * NNODES + q0 + rhi];
#pragma unroll
        for (int nb = 0; nb < 7; nb++) {
            if (nb >= NB) continue;
            int c0 = (base_nb + nb) * 8 + 2 * ac;
            float v0 = fmaxf(da[nb][0], 0.f) + dtab[dg_lo * DH + c0];
            float v1 = fmaxf(da[nb][1], 0.f) + dtab[dg_lo * DH + c0 + 1];
            float v2 = fmaxf(da[nb][2], 0.f) + dtab[dg_hi * DH + c0];
            float v3 = fmaxf(da[nb][3], 0.f) + dtab[dg_hi * DH + c0 + 1];
            float s0 = v0 + v2, s1 = v1 + v3;
            s0 += __shfl_xor_sync(0xffffffffu, s0, 4);
            s1 += __shfl_xor_sync(0xffffffffu, s1, 4);
            s0 += __shfl_xor_sync(0xffffffffu, s0, 8);
            s1 += __shfl_xor_sync(0xffffffffu, s1, 8);
            s0 += __shfl_xor_sync(0xffffffffu, s0, 16);
            s1 += __shfl_xor_sync(0xffffffffu, s1, 16);
            if (l < 4) {
                int cc = (base_nb + nb) * 8 + 2 * l;
                sS[mb * 208 + cc] = s0;
                sS[mb * 208 + cc + 1] = s1;
            }
        }
    }
    __syncthreads();
    if (t < DH) {
        float s = sS[t] + sS[208 + t];
        g_part[side][b][qx][t] = s;
    }
}

// ---------------- fused readout ----------------
__global__ void __launch_bounds__(256) k_readout(
        const float* __restrict__ i1, const float* __restrict__ i2,
        const float* __restrict__ W1, const float* __restrict__ b1,
        const float* __restrict__ W2, const float* __restrict__ b2,
        const float* __restrict__ W3, const float* __restrict__ b3,
        const float* __restrict__ W4, const float* __restrict__ b4,
        float* __restrict__ out) {
    __shared__ float sx[618], s1[400], s2[200], s3[104];
    int b = blockIdx.x, t = threadIdx.x;
    if (t < DH) {
        float m1 = 0.f, m2 = 0.f;
#pragma unroll
        for (int tile = 0; tile < 16; tile++) {
            m1 += g_part[0][b][tile][t];
            m2 += g_part[1][b][tile][t];
        }
        m1 *= (1.0f / NNODES); m2 *= (1.0f / NNODES);
        sx[t] = m1; sx[206 + t] = m2; sx[412 + t] = m1 - m2;
    } else if (t < DH + DI) {
        int j = t - DH;
        float m1 = 0.f, m2 = 0.f;
#pragma unroll 4
        for (int n = 0; n < NNODES; n++) {
            m1 += i1[(b * NNODES + n) * DI + j];
            m2 += i2[(b * NNODES + n) * DI + j];
        }
        m1 *= (1.0f / NNODES); m2 *= (1.0f / NNODES);
        sx[200 + j] = m1; sx[406 + j] = m2; sx[612 + j] = m1 - m2;
    }
    __syncthreads();
    for (int o = t; o < 400; o += 256) {
        float a = b1[o];
        for (int j = 0; j < 618; j++) a = fmaf(sx[j], W1[j * 400 + o], a);
        s1[o] = fmaxf(a, 0.f);
    }
    __syncthreads();
    for (int o = t; o < 200; o += 256) {
        float a = b2[o];
        for (int j = 0; j < 400; j++) a = fmaf(s1[j], W2[j * 200 + o], a);
        s2[o] = fmaxf(a, 0.f);
    }
    __syncthreads();
    for (int o = t; o < 100; o += 256) {
        float a = b3[o];
        for (int j = 0; j < 200; j++) a = fmaf(s2[j], W3[j * 100 + o], a);
        s3[o] = fmaxf(a, 0.f);
    }
    __syncthreads();
    if (t < 32) {
        float a = 0.f;
        for (int j = t; j < 100; j += 32) a = fmaf(s3[j], W4[j], a);
#pragma unroll
        for (int o = 16; o > 0; o >>= 1) a += __shfl_xor_sync(0xffffffffu, a, o);
        if (t == 0) out[b] = a + b4[0];
    }
}

// ---------------- launch ----------------
extern "C" void kernel_launch(void* const* d_in, const int* in_sizes, int n_in,
                              void* d_out, int out_size) {
    const float* atom1  = (const float*)d_in[0];
    const float* atom2  = (const float*)d_in[1];
    const float* coords1 = (const float*)d_in[2];
    const float* coords2 = (const float*)d_in[3];
    const float* ef1    = (const float*)d_in[4];
    const float* ef2    = (const float*)d_in[5];
    const float* int1   = (const float*)d_in[6];
    const float* int2   = (const float*)d_in[7];
    const int*   src1   = (const int*)d_in[8];
    const int*   dst1   = (const int*)d_in[9];
    const int*   src2   = (const int*)d_in[10];
    const int*   dst2   = (const int*)d_in[11];
    const float* W_atom = (const float*)d_in[12];
    const float* W_edge = (const float*)d_in[13];
    const float* W_rbf  = (const float*)d_in[14];
    const float* b_rbf  = (const float*)d_in[15];
    const float* ln_g   = (const float*)d_in[16];
    const float* ln_b   = (const float*)d_in[17];
    const float* W_down = (const float*)d_in[18];
    const float* dtab   = (const float*)d_in[19];
    const float* W_f1   = (const float*)d_in[20];
    const float* b_f1   = (const float*)d_in[21];
    const float* W_f2   = (const float*)d_in[22];
    const float* b_f2   = (const float*)d_in[23];
    const float* W_f3   = (const float*)d_in[24];
    const float* b_f3   = (const float*)d_in[25];
    const float* W_f4   = (const float*)d_in[26];
    const float* b_f4   = (const float*)d_in[27];
    float* out = (float*)d_out;

    const int SMEM_ATOM = (DA * DH + 8 * 2 * DA) * 4;
    const int SMEM_ATTN = (ATM * QSTR + ATK * QSTR + ATM * SSTR + 3 * ATM) * 4;  // 87424

    cudaFuncSetAttribute(k_atom, cudaFuncAttributeMaxDynamicSharedMemorySize, SMEM_ATOM);
    cudaFuncSetAttribute(k_attn, cudaFuncAttributeMaxDynamicSharedMemorySize, SMEM_ATTN);

    dim3 gatom(1024, 2);
    k_atom<<<gatom, 256, SMEM_ATOM>>>(atom1, atom2, dst1, dst2, W_atom, ln_g, ln_b);
    k_scanfill<<<1026, 1024>>>(dst1, dst2);
    dim3 ggath(1024, 2);
    k_gather<<<ggath, 128>>>(ef1, ef2, coords1, coords2, src1, src2,
                             W_edge, W_rbf, b_rbf, ln_g, ln_b);
    dim3 agrid(NNODES / ATM, BB, 2);
    k_attn<<<agrid, 256, SMEM_ATTN>>>(W_down, dtab);
    k_readout<<<BB, 256>>>(int1, int2, W_f1, b_f1, W_f2, b_f2,
                           W_f3, b_f3, W_f4, b_f4, out);
}